// round 14
// baseline (speedup 1.0000x reference)
#include <cuda_runtime.h>
#include <math.h>

// BTNetEuropean closed form:
//   out[b] = sum_j C(N,j) w0^{N-j} w1^j * relu(k[b]*w_init[j] + b_init[j])
// x_j monotone decreasing in j => relu mask is a prefix:
//   out[b] = (k*PW[j*] + PB[j*]) * scale,  j* = #{j : x_j > 0}.
//
// R14: NO cross-block handoff. 8 blocks x 1024 threads; EVERY block builds
// the prefix tables in its own SHARED memory (R13's 2-barrier mantissa/
// exponent scan, ~600cyc of shfl chains — cheap enough to replicate) and
// prices its 1024 batch elements from LDS. w_init/b_init are staged to
// shared during the scan, so the verification probes are LDS too. Critical
// path: ONE global load round -> scan -> barrier -> 2 LDS + FMA + STG.
// No __device__ state, no flag/fence/atomics — fully deterministic.

#define N_DIM   1024
#define N_NODES 1025
#define BATCH   8192
#define NT      1024

__global__ __launch_bounds__(NT)
void fused_kernel(const float* __restrict__ k,
                  const float* __restrict__ w_init,
                  const float* __restrict__ b_init,
                  const float* __restrict__ w,
                  float* __restrict__ out)
{
    __shared__ float2 s_T[N_NODES + 1];   // exclusive prefix {PW, PB}, UNscaled
    __shared__ float  s_wi[N_NODES];
    __shared__ float  s_bi[N_NODES];
    __shared__ float  s_m[32];
    __shared__ int    s_e[32];            // warp TOTAL exponent
    __shared__ int    s_x[32];            // warp MAX exponent
    __shared__ float  s_A[3][32];
    __shared__ float  s_f[32];
    __shared__ float  s_O[3][32];
    __shared__ float  s_scale;

    const int tid  = threadIdx.x;
    const int lane = tid & 31;
    const int wid  = tid >> 5;
    const unsigned FULL = 0xFFFFFFFFu;

    // ---- round 1: ALL global loads issued together ----
    const int   b   = blockIdx.x * NT + tid;        // 8 * 1024 = BATCH
    const float kv  = __ldg(&k[b]);
    const float w0  = __ldg(&w[0]);
    const float w1  = __ldg(&w[1]);
    const float wiv = __ldg(&w_init[tid + 1]);
    const float biv = __ldg(&b_init[tid + 1]);
    const float wi0 = __ldg(&w_init[0]);
    const float bi0 = __ldg(&b_init[0]);
    const float biN = __ldg(&b_init[N_DIM]);

    // stage tables for LDS probes
    s_wi[tid + 1] = wiv;
    s_bi[tid + 1] = biv;
    if (tid == 0) { s_wi[0] = wi0; s_bi[0] = bi0; }

    const float rw = w1 / w0;

    // analytic normalizer E0 ~= log2(c_max/c_0) via Stirling (fp32).
    // Only needs +-30 bits; compensated exactly by the final scale.
    float p    = rw / (1.0f + rw);
    float m0f  = rintf(1024.0f * p);
    float H2   = -p * log2f(p) - (1.0f - p) * log2f(1.0f - p);
    float l2C  = 1024.0f * H2
               - 0.5f * log2f(6.2831853f * 1024.0f * p * (1.0f - p));
    const int E0 = (int)(l2C + m0f * log2f(rw)) + 2;

    // analytic j* guess (independent of tables; hidden under the scan):
    // ln(-b_init[j]) is affine in j.
    float L0    = logf(-bi0);
    float LN    = logf(-biN);
    float slope = (LN - L0) * (1.0f / (float)N_DIM);
    float jf    = (logf(kv) - L0) / slope;
    int g;
    if (jf >= 0.0f) {                     // NaN-safe: NaN -> g = 0
        g = (jf >= (float)N_NODES) ? N_NODES : (int)ceilf(jf);
    } else {
        g = 0;
    }

    // thread 1023: (w0+w1)^1024 in double-float (early, ILP-covered)
    float pw_hi = 0.0f, pw_lo = 0.0f;
    if (tid == NT - 1) {
        float sh = w0 + w1;
        float sl = (w0 - sh) + w1;        // TwoSum error term
        #pragma unroll
        for (int i = 0; i < 10; i++) {    // df squaring x10
            float ph = sh * sh;
            float pe = fmaf(sh, sh, -ph);
            float pl = fmaf(2.0f * sh, sl, pe);
            float t  = ph + pl;
            pl = (ph - t) + pl;
            sh = t; sl = pl;
        }
        pw_hi = sh; pw_lo = sl;
    }

    // ---- Phase A: warp product scan of rho + warp-max norm + triple sum ----
    float rho = ((float)(N_DIM - tid) / (float)(tid + 1)) * rw;
    int e; float m = frexpf(rho, &e);
    #pragma unroll
    for (int d = 1; d < 32; d <<= 1) {
        float mo = __shfl_up_sync(FULL, m, d);
        int   eo = __shfl_up_sync(FULL, e, d);
        if (lane >= d) {
            m *= mo; e += eo;
            if (m < 0.5f) { m *= 2.0f; e -= 1; }
        }
    }
    // warp max exponent X_w (overflow-safe local normalizer)
    int xw = e;
    #pragma unroll
    for (int d = 16; d; d >>= 1)
        xw = max(xw, __shfl_xor_sync(FULL, xw, d));

    float cl = ldexpf(m, e - xw);         // <= 1, no overflow
    float a0 = cl, a1 = cl * wiv, a2 = cl * biv;
    #pragma unroll
    for (int d = 1; d < 32; d <<= 1) {
        float t0 = __shfl_up_sync(FULL, a0, d);
        float t1 = __shfl_up_sync(FULL, a1, d);
        float t2 = __shfl_up_sync(FULL, a2, d);
        if (lane >= d) { a0 += t0; a1 += t1; a2 += t2; }
    }
    if (lane == 31) {
        s_m[wid] = m;  s_e[wid] = e;      // warp TOTAL (m, e)
        s_x[wid] = xw;                    // warp MAX exponent
        s_A[0][wid] = a0; s_A[1][wid] = a1; s_A[2][wid] = a2;
    }
    __syncthreads();

    // ---- Phase B: single warp0 section ----
    if (wid == 0) {
        float Mw = s_m[lane];
        int   Ew = s_e[lane];
        const int xww = s_x[lane];
        float A0 = s_A[0][lane], A1 = s_A[1][lane], A2 = s_A[2][lane];

        // inclusive product scan of warp totals
        #pragma unroll
        for (int d = 1; d < 32; d <<= 1) {
            float mo = __shfl_up_sync(FULL, Mw, d);
            int   eo = __shfl_up_sync(FULL, Ew, d);
            if (lane >= d) {
                Mw *= mo; Ew += eo;
                if (Mw < 0.5f) { Mw *= 2.0f; Ew -= 1; }
            }
        }
        // exclusive product prefix
        float Mx = __shfl_up_sync(FULL, Mw, 1);
        int   Ex = __shfl_up_sync(FULL, Ew, 1);
        if (lane == 0) { Mx = 0.5f; Ex = 1; }      // identity (1.0)

        // per-warp factor: f_w = Pexcl_w * 2^(X_w - E0)
        float f = ldexpf(Mx, Ex + xww - E0);

        // exclusive sum scan of f * warp sums (triple)
        float t0 = f * A0, t1 = f * A1, t2 = f * A2;
        float i0 = t0, i1 = t1, i2 = t2;
        #pragma unroll
        for (int d = 1; d < 32; d <<= 1) {
            float u0 = __shfl_up_sync(FULL, i0, d);
            float u1 = __shfl_up_sync(FULL, i1, d);
            float u2 = __shfl_up_sync(FULL, i2, d);
            if (lane >= d) { i0 += u0; i1 += u1; i2 += u2; }
        }
        s_f[lane]    = f;
        s_O[0][lane] = i0 - t0;    // exclusive offsets
        s_O[1][lane] = i1 - t1;
        s_O[2][lane] = i2 - t2;
    }
    __syncthreads();

    // ---- Phase C: combine + publish to SHARED ----
    const float f  = s_f[wid];
    const float G0 = fmaf(f, a0, s_O[0][wid]);   // inclusive 1..tid+1
    const float G1 = fmaf(f, a1, s_O[1][wid]);
    const float G2 = fmaf(f, a2, s_O[2][wid]);

    const float c0 = ldexpf(1.0f, -E0);   // chat_0 (usually flushes to 0)
    const float bw = c0 * wi0;
    const float bb = c0 * bi0;

    // s_T[i] = UNscaled exclusive prefix over j < i; thread t -> entry t+2
    s_T[tid + 2] = make_float2(bw + G1, bb + G2);
    if (tid == 0) {
        s_T[0] = make_float2(0.0f, 0.0f);
        s_T[1] = make_float2(bw, bb);
    }
    if (tid == NT - 1) {
        float totC = c0 + G0;             // sum of all c~
        float q = pw_hi / totC;           // df-refined divide
        q += (fmaf(-q, totC, pw_hi) + pw_lo) / totC;
        s_scale = q;                      // scale = (w0+w1)^N / S
    }
    __syncthreads();

    // ---- price: verify guess with LDS probes, then table lookup ----
    float xg  = (g <  N_NODES)
              ? fmaf(kv, s_wi[g],     s_bi[g])     : -1.0f;
    float xgm = (g > 0)
              ? fmaf(kv, s_wi[g - 1], s_bi[g - 1]) :  1.0f;

    // monotone fix-up (rarely iterates; correct for any monotone input)
    if (xg > 0.0f) {
        do { g++; } while (g < N_NODES &&
            fmaf(kv, s_wi[g], s_bi[g]) > 0.0f);
    } else if (xgm <= 0.0f) {
        do { g--; } while (g > 0 &&
            fmaf(kv, s_wi[g - 1], s_bi[g - 1]) <= 0.0f);
    }

    float2 t = s_T[g];
    out[b] = fmaf(kv, t.x, t.y) * s_scale;
}

extern "C" void kernel_launch(void* const* d_in, const int* in_sizes, int n_in,
                              void* d_out, int out_size)
{
    const float* k      = (const float*)d_in[0];   // (8192,)
    const float* w_init = (const float*)d_in[1];   // (1025,)
    const float* b_init = (const float*)d_in[2];   // (1025,)
    const float* w      = (const float*)d_in[3];   // (2,)
    float*       out    = (float*)d_out;           // (8192,)

    (void)in_sizes; (void)n_in; (void)out_size;

    fused_kernel<<<BATCH / NT, NT>>>(k, w_init, b_init, w, out);
}

// round 15
// speedup vs baseline: 1.1102x; 1.1102x over previous
#include <cuda_runtime.h>
#include <math.h>

// BTNetEuropean closed form:
//   out[b] = sum_j C(N,j) w0^{N-j} w1^j * relu(k[b]*w_init[j] + b_init[j])
// x_j monotone decreasing in j => relu mask is a prefix:
//   out[b] = (k*PW[j*] + PB[j*]) * scale,  j* = #{j : x_j > 0}.
//
// R15: spread issue volume. 64 blocks x 128 threads (64 SMs, 4 warps/SM vs
// 8 SMs x 32 warps — R14 showed issue-bound at unramped clock). Each thread
// owns a SERIAL chunk of 8 ratios (fp32 product, chunk range <= 2^65, one
// frexpf at the end); 4-warp scans with cross-warp combine done LOCALLY by
// every thread (no warp0 serial section); 3 barriers. Same E0-Stirling
// normalization + exact (w0+w1)^N/sum compensation as R13/R14. Pricing:
// 1 element/thread, analytic j* guess + LDS probes (validated R10-R14).
// No __device__ state — fully deterministic, no cross-block traffic.

#define N_DIM   1024
#define N_NODES 1025
#define BATCH   8192
#define NT      128
#define EPT     8          // table elements per thread (NT*EPT = 1024)

__global__ __launch_bounds__(NT)
void fused_kernel(const float* __restrict__ k,
                  const float* __restrict__ w_init,
                  const float* __restrict__ b_init,
                  const float* __restrict__ w,
                  float* __restrict__ out)
{
    __shared__ float s_Tw[N_NODES + 1];   // exclusive prefix of c*wi (+bw)
    __shared__ float s_Tb[N_NODES + 1];   // exclusive prefix of c*bi (+bb)
    __shared__ float s_wi[N_NODES];
    __shared__ float s_bi[N_NODES];
    __shared__ float s_m[4];
    __shared__ int   s_e[4];
    __shared__ float s_S[3][4];
    __shared__ float s_pw[2];
    __shared__ float s_scale;

    const int tid  = threadIdx.x;
    const int lane = tid & 31;
    const int wid  = tid >> 5;            // 0..3
    const unsigned FULL = 0xFFFFFFFFu;

    // ---- round 1: ALL global loads issued together ----
    const int   b   = blockIdx.x * NT + tid;      // 64 * 128 = BATCH
    const float kv  = __ldg(&k[b]);
    const float w0  = __ldg(&w[0]);
    const float w1  = __ldg(&w[1]);
    const float wi0 = __ldg(&w_init[0]);
    const float bi0 = __ldg(&b_init[0]);
    const float biN = __ldg(&b_init[N_DIM]);

    const int i0 = tid * EPT;                     // ratio indices i0..i0+7
    float wiL[EPT], biL[EPT];
    #pragma unroll
    for (int j = 0; j < EPT; j++) {
        wiL[j] = __ldg(&w_init[i0 + 1 + j]);
        biL[j] = __ldg(&b_init[i0 + 1 + j]);
    }

    const float rw = w1 / w0;

    // analytic normalizer E0 ~= log2(c_max/c_0) via Stirling (fp32);
    // only needs +-30 bits, exactly compensated by the final scale.
    float p    = rw / (1.0f + rw);
    float m0f  = rintf(1024.0f * p);
    float H2   = -p * log2f(p) - (1.0f - p) * log2f(1.0f - p);
    float l2C  = 1024.0f * H2
               - 0.5f * log2f(6.2831853f * 1024.0f * p * (1.0f - p));
    const int E0 = (int)(l2C + m0f * log2f(rw)) + 2;

    // analytic j* guess (independent of tables, hidden under the scan):
    // ln(-b_init[j]) is affine in j.
    float L0    = logf(-bi0);
    float LN    = logf(-biN);
    float slope = (LN - L0) * (1.0f / (float)N_DIM);
    float jf    = (logf(kv) - L0) / slope;
    int g;
    if (jf >= 0.0f) {                     // NaN-safe: NaN -> g = 0
        g = (jf >= (float)N_NODES) ? N_NODES : (int)ceilf(jf);
    } else {
        g = 0;
    }

    // thread 0: (w0+w1)^1024 in double-float; publish before BAR1
    if (tid == 0) {
        float sh = w0 + w1;
        float sl = (w0 - sh) + w1;        // TwoSum error term
        #pragma unroll
        for (int i = 0; i < 10; i++) {    // df squaring x10
            float ph = sh * sh;
            float pe = fmaf(sh, sh, -ph);
            float pl = fmaf(2.0f * sh, sl, pe);
            float t  = ph + pl;
            pl = (ph - t) + pl;
            sh = t; sl = pl;
        }
        s_pw[0] = sh; s_pw[1] = sl;
    }

    // ---- Phase A: serial product of 8 ratios, then 4-warp (m,e) scan ----
    float pp[EPT];
    float P = 1.0f;
    #pragma unroll
    for (int j = 0; j < EPT; j++) {
        int   i   = i0 + j;
        float rho = ((float)(N_DIM - i) / (float)(i + 1)) * rw;
        P *= rho;                          // chunk product stays in 2^+-65
        pp[j] = P;                         // inclusive-within-thread product
    }
    int e; float m = frexpf(P, &e);

    // warp inclusive product scan of thread products
    float mi = m; int ei = e;
    #pragma unroll
    for (int d = 1; d < 32; d <<= 1) {
        float mo = __shfl_up_sync(FULL, mi, d);
        int   eo = __shfl_up_sync(FULL, ei, d);
        if (lane >= d) {
            mi *= mo; ei += eo;
            if (mi < 0.5f) { mi *= 2.0f; ei -= 1; }
        }
    }
    // exclusive-within-warp
    float mex = __shfl_up_sync(FULL, mi, 1);
    int   eex = __shfl_up_sync(FULL, ei, 1);
    if (lane == 0) { mex = 0.5f; eex = 1; }       // identity (1.0)
    if (lane == 31) { s_m[wid] = mi; s_e[wid] = ei; }   // warp totals

    // stage tables for LDS probes (independent of scan)
    #pragma unroll
    for (int j = 0; j < EPT; j++) {
        s_wi[i0 + 1 + j] = wiL[j];
        s_bi[i0 + 1 + j] = biL[j];
    }
    if (tid == 0) { s_wi[0] = wi0; s_bi[0] = bi0; }
    __syncthreads();                               // BAR1

    // cross-warp exclusive product, computed locally by EVERY thread
    float Mc = mex; int Ec = eex;
    #pragma unroll
    for (int ww = 0; ww < 3; ww++) {
        if (ww < wid) { Mc *= s_m[ww]; Ec += s_e[ww]; }
    }
    { int ee2; Mc = frexpf(Mc, &ee2); Ec += ee2; } // renormalize once

    // f = (exclusive product through ratio i0-1) * 2^-E0 = c_{i0} * 2^-E0
    const float f = ldexpf(Mc, Ec - E0);

    // per-element normalized coefficients + thread triple sums
    float cw[EPT], cb[EPT];
    float t0 = 0.0f, t1 = 0.0f, t2 = 0.0f;
    #pragma unroll
    for (int j = 0; j < EPT; j++) {
        float c = f * pp[j];               // c_{i0+1+j} * 2^-E0
        cw[j] = c * wiL[j];
        cb[j] = c * biL[j];
        t0 += c; t1 += cw[j]; t2 += cb[j];
    }

    // warp inclusive triple sum scan
    float a0 = t0, a1 = t1, a2 = t2;
    #pragma unroll
    for (int d = 1; d < 32; d <<= 1) {
        float u0 = __shfl_up_sync(FULL, a0, d);
        float u1 = __shfl_up_sync(FULL, a1, d);
        float u2 = __shfl_up_sync(FULL, a2, d);
        if (lane >= d) { a0 += u0; a1 += u1; a2 += u2; }
    }
    if (lane == 31) { s_S[0][wid] = a0; s_S[1][wid] = a1; s_S[2][wid] = a2; }
    __syncthreads();                               // BAR2

    // cross-warp exclusive offsets, locally by every thread
    float O0 = a0 - t0, O1 = a1 - t1, O2 = a2 - t2;   // excl within warp
    #pragma unroll
    for (int ww = 0; ww < 3; ww++) {
        if (ww < wid) { O0 += s_S[0][ww]; O1 += s_S[1][ww]; O2 += s_S[2][ww]; }
    }

    const float c0 = ldexpf(1.0f, -E0);   // chat_0 (usually flushes to 0)
    const float bw = c0 * wi0;
    const float bb = c0 * bi0;

    // publish table entries: s_T[i] = bw/bb + prefix over elements 1..i-1.
    // Thread t owns entries i0+2 .. i0+9 (running prefix through its chunk).
    float r1 = O1, r2 = O2;
    #pragma unroll
    for (int j = 0; j < EPT; j++) {
        r1 += cw[j]; r2 += cb[j];
        s_Tw[i0 + 2 + j] = bw + r1;
        s_Tb[i0 + 2 + j] = bb + r2;
    }
    if (tid == 0) {
        s_Tw[0] = 0.0f; s_Tb[0] = 0.0f;
        s_Tw[1] = bw;   s_Tb[1] = bb;
    }
    if (tid == NT - 1) {
        float totC = c0 + O0 + t0;         // sum of all c~
        float q = s_pw[0] / totC;          // df-refined divide
        q += (fmaf(-q, totC, s_pw[0]) + s_pw[1]) / totC;
        s_scale = q;                       // scale = (w0+w1)^N / S
    }
    __syncthreads();                               // BAR3

    // ---- price: verify guess with LDS probes, then table lookup ----
    float xg  = (g <  N_NODES)
              ? fmaf(kv, s_wi[g],     s_bi[g])     : -1.0f;
    float xgm = (g > 0)
              ? fmaf(kv, s_wi[g - 1], s_bi[g - 1]) :  1.0f;

    // monotone fix-up (rarely iterates; correct for any monotone input)
    if (xg > 0.0f) {
        do { g++; } while (g < N_NODES &&
            fmaf(kv, s_wi[g], s_bi[g]) > 0.0f);
    } else if (xgm <= 0.0f) {
        do { g--; } while (g > 0 &&
            fmaf(kv, s_wi[g - 1], s_bi[g - 1]) <= 0.0f);
    }

    out[b] = fmaf(kv, s_Tw[g], s_Tb[g]) * s_scale;
}

extern "C" void kernel_launch(void* const* d_in, const int* in_sizes, int n_in,
                              void* d_out, int out_size)
{
    const float* k      = (const float*)d_in[0];   // (8192,)
    const float* w_init = (const float*)d_in[1];   // (1025,)
    const float* b_init = (const float*)d_in[2];   // (1025,)
    const float* w      = (const float*)d_in[3];   // (2,)
    float*       out    = (float*)d_out;           // (8192,)

    (void)in_sizes; (void)n_in; (void)out_size;

    fused_kernel<<<BATCH / NT, NT>>>(k, w_init, b_init, w, out);
}